// round 15
// baseline (speedup 1.0000x reference)
#include <cuda_runtime.h>
#include <cuda_fp16.h>
#include <math.h>
#include <stdint.h>

// ---------------- problem constants ----------------
#define BTOK   32768
#define DIMSZ  1024
#define NEXP   8
#define TOPK   2
#define HID    4096
#define CAPCT  10240            // ceil(1.25 * 32768 * 2 / 8)
#define NSLOT  (BTOK * TOPK)    // 65536

// ---------------- GEMM tiling ----------------
#define BM 128
#define BN 128
#define BK 64                   // K elements per chunk (fp16) -> 128B rows
#define ROWB 144                // padded row stride bytes (128 data + 16 pad)
#define RG_A  0
#define RG_B  18432             // 128 rows * 144
#define STG_BYTES 36864
#define NSTAGE 3
#define SMEM_G (NSTAGE * STG_BYTES)   // 110592, dynamic (opt-in)

// ---------------- device scratch (static, no allocs) ----------------
__device__ __align__(128) __half g_x16[(size_t)BTOK * DIMSZ];
__device__ __align__(128) __half g_w1t[(size_t)NEXP * HID * DIMSZ]; // [e][n=hid][k=dim]
__device__ __align__(128) __half g_w2t[(size_t)NEXP * DIMSZ * HID]; // [e][n=dim][k=hid]
__device__ __align__(128) __half g_h16[(size_t)NEXP * CAPCT * HID];
__device__ __align__(128) int                g_tok[NEXP * CAPCT];
__device__ __align__(128) float              g_gw[NEXP * CAPCT];
__device__ __align__(128) int                g_topi[NSLOT];
__device__ __align__(128) float              g_topw[NSLOT];
__device__ int                g_count[NEXP];
__device__ int                g_len[NEXP];
__device__ float              g_usage[NEXP];
__device__ float              g_z2;
__device__ unsigned long long g_thr[NEXP];

// ---------------- helpers ----------------
__device__ __forceinline__ uint32_t smem_u32(const void* p) {
    uint32_t a;
    asm("{ .reg .u64 t; cvta.to.shared.u64 t, %1; cvt.u32.u64 %0, t; }" : "=r"(a) : "l"(p));
    return a;
}
__device__ __forceinline__ void cp16(uint32_t d, const void* s) {
    asm volatile("cp.async.cg.shared.global [%0], [%1], 16;" :: "r"(d), "l"(s));
}
__device__ __forceinline__ void cp_commit() { asm volatile("cp.async.commit_group;"); }
__device__ __forceinline__ void cp_wait1()  { asm volatile("cp.async.wait_group 1;"); }

__device__ __forceinline__ void ldsm4(uint32_t* r, uint32_t a) {
    asm volatile("ldmatrix.sync.aligned.m8n8.x4.shared.b16 {%0,%1,%2,%3}, [%4];"
                 : "=r"(r[0]), "=r"(r[1]), "=r"(r[2]), "=r"(r[3]) : "r"(a));
}
__device__ __forceinline__ void mma_f16(float* d, const uint32_t* a, uint32_t b0, uint32_t b1) {
    asm volatile("mma.sync.aligned.m16n8k16.row.col.f32.f16.f16.f32 "
                 "{%0,%1,%2,%3}, {%4,%5,%6,%7}, {%8,%9}, {%0,%1,%2,%3};"
                 : "+f"(d[0]), "+f"(d[1]), "+f"(d[2]), "+f"(d[3])
                 : "r"(a[0]), "r"(a[1]), "r"(a[2]), "r"(a[3]), "r"(b0), "r"(b1));
}

__device__ __forceinline__ unsigned long long make_key(float w, int slot) {
    return ((unsigned long long)__float_as_uint(w) << 32) |
           (unsigned long long)(0xFFFFFFFFu - (unsigned)slot);
}
__device__ __forceinline__ float gelu_exact(float v) {
    return 0.5f * v * (1.0f + erff(v * 0.70710678118654752f));
}

// ---------------- init ----------------
__global__ void init_kernel() {
    int t = threadIdx.x;
    if (t < NEXP) { g_count[t] = 0; g_len[t] = 0; g_usage[t] = 0.f; }
    if (t == 0)   { g_z2 = 0.f; }
}

// ---------------- conversions ----------------
__global__ __launch_bounds__(256) void conv_x_kernel(const float* __restrict__ x) {
    size_t i = (size_t)blockIdx.x * 256 + threadIdx.x;        // float4 index
    float4 v = ((const float4*)x)[i];
    __half2 p0 = __floats2half2_rn(v.x, v.y);
    __half2 p1 = __floats2half2_rn(v.z, v.w);
    ((__half2*)g_x16)[i * 2 + 0] = p0;
    ((__half2*)g_x16)[i * 2 + 1] = p1;
}

// transpose: src [e][K_][N_] fp32 -> dst [e][N_][K_] fp16
// Destination globals bound INSIDE device code (host-passed __device__ symbols
// resolve to the host shadow -> silent ATS writes on GB300; R4/R6 bug).
__global__ __launch_bounds__(256) void conv_tr_kernel(const float* __restrict__ src,
                                                      int which, int K_, int N_) {
    __half* dst = which ? g_w2t : g_w1t;
    __shared__ float t[32][33];
    int e = blockIdx.z;
    src += (size_t)e * K_ * N_;
    dst += (size_t)e * K_ * N_;
    int n0 = blockIdx.x * 32, k0 = blockIdx.y * 32;
    int tx = threadIdx.x & 31, ty = threadIdx.x >> 5;
#pragma unroll
    for (int i = 0; i < 32; i += 8)
        t[ty + i][tx] = src[(size_t)(k0 + ty + i) * N_ + n0 + tx];
    __syncthreads();
#pragma unroll
    for (int i = 0; i < 32; i += 8) {
        float v = t[tx][ty + i];
        dst[(size_t)(n0 + ty + i) * K_ + k0 + tx] = __float2half_rn(v);
    }
}

// ---------------- router ----------------
__global__ __launch_bounds__(256) void router_kernel(const float* __restrict__ x,
                                                     const float* __restrict__ rw) {
    __shared__ float sW[NEXP * DIMSZ];
    __shared__ float s_usage[NEXP];
    __shared__ int   s_count[NEXP];
    __shared__ float s_z2;

    int tid = threadIdx.x;
    for (int i = tid; i < NEXP * DIMSZ; i += 256) sW[i] = rw[i];
    if (tid < NEXP) { s_usage[tid] = 0.f; s_count[tid] = 0; }
    if (tid == 0) s_z2 = 0.f;
    __syncthreads();

    int warp = tid >> 5, lane = tid & 31;
    for (int t = 0; t < 4; t++) {
        int row = blockIdx.x * 32 + warp * 4 + t;
        const float* xr = x + (size_t)row * DIMSZ;
        float acc[NEXP];
#pragma unroll
        for (int e = 0; e < NEXP; e++) acc[e] = 0.f;
        for (int i = lane; i < DIMSZ; i += 32) {
            float xv = xr[i];
#pragma unroll
            for (int e = 0; e < NEXP; e++) acc[e] = fmaf(xv, sW[e * DIMSZ + i], acc[e]);
        }
#pragma unroll
        for (int e = 0; e < NEXP; e++)
#pragma unroll
            for (int off = 16; off; off >>= 1)
                acc[e] += __shfl_xor_sync(0xFFFFFFFFu, acc[e], off);

        if (lane == 0) {
            float m = acc[0];
#pragma unroll
            for (int e = 1; e < NEXP; e++) m = fmaxf(m, acc[e]);
            float p[NEXP]; float se = 0.f;
#pragma unroll
            for (int e = 0; e < NEXP; e++) { p[e] = expf(acc[e] - m); se += p[e]; }
            float inv = 1.f / se;
#pragma unroll
            for (int e = 0; e < NEXP; e++) p[e] *= inv;
            float z = m + logf(se);

            int i0 = 0;
#pragma unroll
            for (int e = 1; e < NEXP; e++) if (acc[e] > acc[i0]) i0 = e;
            int i1 = -1;
#pragma unroll
            for (int e = 0; e < NEXP; e++)
                if (e != i0 && (i1 < 0 || acc[e] > acc[i1])) i1 = e;

            float p0 = p[i0], p1 = p[i1];
            float s = fmaxf(p0 + p1, 1e-9f);
            g_topi[row * 2 + 0] = i0; g_topw[row * 2 + 0] = p0 / s;
            g_topi[row * 2 + 1] = i1; g_topw[row * 2 + 1] = p1 / s;

            atomicAdd(&s_count[i0], 1);
            atomicAdd(&s_count[i1], 1);
#pragma unroll
            for (int e = 0; e < NEXP; e++) atomicAdd(&s_usage[e], p[e]);
            atomicAdd(&s_z2, z * z);
        }
    }
    __syncthreads();
    if (tid < NEXP) {
        atomicAdd(&g_usage[tid], s_usage[tid]);
        atomicAdd(&g_count[tid], s_count[tid]);
    }
    if (tid == 0) atomicAdd(&g_z2, s_z2);
}

// ---------------- exact capacity threshold (radix select, only on overflow) ----------------
__global__ void select_kernel() {
    int e = blockIdx.x;
    if (g_count[e] <= CAPCT) {
        if (threadIdx.x == 0) g_thr[e] = 0ULL;
        return;
    }
    __shared__ unsigned int       hist[256];
    __shared__ unsigned long long s_prefix;
    __shared__ int                s_rem;
    if (threadIdx.x == 0) { s_prefix = 0ULL; s_rem = CAPCT; }

    for (int pass = 7; pass >= 0; pass--) {
        __syncthreads();
        for (int i = threadIdx.x; i < 256; i += blockDim.x) hist[i] = 0u;
        __syncthreads();
        unsigned long long prefix = s_prefix;
        for (int s = threadIdx.x; s < NSLOT; s += blockDim.x) {
            if (g_topi[s] == e) {
                unsigned long long key = make_key(g_topw[s], s);
                bool match = (pass == 7) || ((key >> ((pass + 1) * 8)) == prefix);
                if (match)
                    atomicAdd(&hist[(unsigned)((key >> (pass * 8)) & 255ULL)], 1u);
            }
        }
        __syncthreads();
        if (threadIdx.x == 0) {
            int rem = s_rem;
            int digit = 0;
            for (int b = 255; b >= 0; b--) {
                if ((int)hist[b] >= rem) { digit = b; break; }
                rem -= (int)hist[b];
            }
            s_prefix = (s_prefix << 8) | (unsigned long long)digit;
            s_rem = rem;
        }
    }
    __syncthreads();
    if (threadIdx.x == 0) g_thr[e] = s_prefix;
}

// ---------------- build per-expert token lists ----------------
__global__ void build_kernel() {
    int s = blockIdx.x * blockDim.x + threadIdx.x;
    if (s >= NSLOT) return;
    int e = g_topi[s];
    float w = g_topw[s];
    bool keep = (g_count[e] <= CAPCT) || (make_key(w, s) >= g_thr[e]);
    if (keep) {
        int pos = atomicAdd(&g_len[e], 1);
        g_tok[e * CAPCT + pos] = s >> 1;
        g_gw[e * CAPCT + pos]  = w;
    }
}

// ======================================================================
// Plain fp16 HMMA GEMM core (fp32 accumulate). BK=64 chunks (128B rows,
// ROWB=144 pad -> conflict-free ldsm), 64 HMMA/warp/chunk -- per-chunk
// sync/pipeline overhead amortized over 2x the MMA work vs BK=32.
// 128x128 CTA tile, 3-stage cp.async pipeline.
// 8 warps: (wm,wn), wm in {0,1} x 64 rows, wn in {0..3} x 32 cols.
// ======================================================================
template <bool IS_G1>
__device__ __forceinline__ void gemm_core(int e, int len, int row0, int col0,
                                          uint32_t sb, float acc[4][4][4]) {
    int tid = threadIdx.x, lane = tid & 31, wid = tid >> 5;
    int wm = wid & 1, wn = wid >> 1;

    // load mapping: row = tid>>1 (0..127), sel = tid&1 (64B half of 128B row)
    int lrow = tid >> 1, lsel = tid & 1;
    const __half *ap, *bp;
    int KTOT;
    if (IS_G1) {
        int gr = row0 + lrow;
        int tok = (gr < len) ? g_tok[e * CAPCT + gr] : 0;
        ap = g_x16 + (size_t)tok * DIMSZ + lsel * 32;
        bp = g_w1t + ((size_t)e * HID + col0 + lrow) * DIMSZ + lsel * 32;
        KTOT = DIMSZ;
    } else {
        ap = g_h16 + ((size_t)e * CAPCT + row0 + lrow) * HID + lsel * 32;
        bp = g_w2t + ((size_t)e * DIMSZ + col0 + lrow) * HID + lsel * 32;
        KTOT = HID;
    }
    const int NK = KTOT / BK;
    uint32_t sdst = sb + lrow * ROWB + lsel * 64;

    auto load_stage = [&](int st, int kc) {
        uint32_t base = sdst + st * STG_BYTES;
#pragma unroll
        for (int q = 0; q < 4; q++) {
            cp16(base + RG_A + q * 16, ap + kc + q * 8);
            cp16(base + RG_B + q * 16, bp + kc + q * 8);
        }
    };

    load_stage(0, 0);   cp_commit();
    load_stage(1, BK);  cp_commit();

    // per-lane ldmatrix base offsets (x4: lanes 0-15 rows, lanes 16-31 +16B k-half)
    uint32_t arow = (uint32_t)(wm * 64 + (lane & 15)) * ROWB + ((lane >> 4) * 16);
    uint32_t brow = (uint32_t)(wn * 32 + (lane & 15)) * ROWB + ((lane >> 4) * 16);

    for (int c = 0; c < NK; c++) {
        int st = c % NSTAGE;
        cp_wait1();          // stage c resident (<=1 newer group outstanding)
        __syncthreads();     // also fences stage (c % NSTAGE) reads from last round
        if (c + 2 < NK) load_stage((c + 2) % NSTAGE, (c + 2) * BK);
        cp_commit();

        uint32_t sbase = sb + st * STG_BYTES;
#pragma unroll
        for (int kk = 0; kk < 4; kk++) {           // four k16 steps per chunk
            uint32_t ah[4][4];
#pragma unroll
            for (int mt = 0; mt < 4; mt++)
                ldsm4(ah[mt], sbase + RG_A + arow + mt * (16 * ROWB) + kk * 32);
            uint32_t bh[2][4];
#pragma unroll
            for (int j = 0; j < 2; j++)
                ldsm4(bh[j], sbase + RG_B + brow + j * (16 * ROWB) + kk * 32);
#pragma unroll
            for (int mt = 0; mt < 4; mt++)
#pragma unroll
                for (int j = 0; j < 2; j++)
#pragma unroll
                    for (int s = 0; s < 2; s++)
                        mma_f16(acc[mt][j * 2 + s], ah[mt], bh[j][s], bh[j][s + 2]);
        }
    }
    __syncthreads();
}

// ---------------- GEMM1: h = gelu(gather(x) @ W1 + b1) ----------------
__global__ __launch_bounds__(256, 1) void gemm1_mma(const float* __restrict__ b1) {
    int e = blockIdx.z;
    int len = g_len[e];
    int row0 = blockIdx.y * BM;
    if (row0 >= len) return;
    int col0 = blockIdx.x * BN;

    extern __shared__ __align__(128) char smem_d[];
    uint32_t sb = smem_u32(smem_d);

    float acc[4][4][4];
#pragma unroll
    for (int i = 0; i < 4; i++)
#pragma unroll
        for (int j = 0; j < 4; j++)
#pragma unroll
            for (int k = 0; k < 4; k++) acc[i][j][k] = 0.f;

    gemm_core<true>(e, len, row0, col0, sb, acc);

    int lane = threadIdx.x & 31, wid = threadIdx.x >> 5;
    int wm = wid & 1, wn = wid >> 1;
    const float* bb = b1 + (size_t)e * HID;
#pragma unroll
    for (int mt = 0; mt < 4; mt++) {
        int rA = row0 + wm * 64 + mt * 16 + (lane >> 2);
        int rB = rA + 8;
        bool vA = rA < len, vB = rB < len;
        __half* hA = g_h16 + ((size_t)e * CAPCT + rA) * HID;
        __half* hB = g_h16 + ((size_t)e * CAPCT + rB) * HID;
#pragma unroll
        for (int nt = 0; nt < 4; nt++) {
            int col = col0 + wn * 32 + nt * 8 + (lane & 3) * 2;
            float bv0 = bb[col], bv1 = bb[col + 1];
            if (vA) {
                float x0 = gelu_exact(acc[mt][nt][0] + bv0);
                float x1 = gelu_exact(acc[mt][nt][1] + bv1);
                *(__half2*)(hA + col) = __floats2half2_rn(x0, x1);
            }
            if (vB) {
                float x0 = gelu_exact(acc[mt][nt][2] + bv0);
                float x1 = gelu_exact(acc[mt][nt][3] + bv1);
                *(__half2*)(hB + col) = __floats2half2_rn(x0, x1);
            }
        }
    }
}

// ---------------- GEMM2: out[tok] += gw * (h @ W2 + b2) ----------------
__global__ __launch_bounds__(256, 1) void gemm2_mma(const float* __restrict__ b2,
                                                    float* __restrict__ out) {
    int e = blockIdx.z;
    int len = g_len[e];
    int row0 = blockIdx.y * BM;
    if (row0 >= len) return;
    int col0 = blockIdx.x * BN;

    extern __shared__ __align__(128) char smem_d[];
    uint32_t sb = smem_u32(smem_d);

    float acc[4][4][4];
#pragma unroll
    for (int i = 0; i < 4; i++)
#pragma unroll
        for (int j = 0; j < 4; j++)
#pragma unroll
            for (int k = 0; k < 4; k++) acc[i][j][k] = 0.f;

    gemm_core<false>(e, len, row0, col0, sb, acc);

    int lane = threadIdx.x & 31, wid = threadIdx.x >> 5;
    int wm = wid & 1, wn = wid >> 1;
    const float* bb = b2 + (size_t)e * DIMSZ;
#pragma unroll
    for (int mt = 0; mt < 4; mt++) {
        int rA = row0 + wm * 64 + mt * 16 + (lane >> 2);
        int rB = rA + 8;
        bool vA = rA < len, vB = rB < len;
        int   tokA = vA ? g_tok[e * CAPCT + rA] : 0;
        float gwA  = vA ? g_gw[e * CAPCT + rA]  : 0.f;
        int   tokB = vB ? g_tok[e * CAPCT + rB] : 0;
        float gwB  = vB ? g_gw[e * CAPCT + rB]  : 0.f;
        float* oA = out + (size_t)tokA * DIMSZ;
        float* oB = out + (size_t)tokB * DIMSZ;
#pragma unroll
        for (int nt = 0; nt < 4; nt++) {
            int col = col0 + wn * 32 + nt * 8 + (lane & 3) * 2;
            float bv0 = bb[col], bv1 = bb[col + 1];
            if (vA) {
                atomicAdd(oA + col,     (acc[mt][nt][0] + bv0) * gwA);
                atomicAdd(oA + col + 1, (acc[mt][nt][1] + bv1) * gwA);
            }
            if (vB) {
                atomicAdd(oB + col,     (acc[mt][nt][2] + bv0) * gwB);
                atomicAdd(oB + col + 1, (acc[mt][nt][3] + bv1) * gwB);
            }
        }
    }
}

// ---------------- aux loss ----------------
__global__ void aux_kernel(float* out, int out_size) {
    if ((size_t)out_size <= (size_t)BTOK * DIMSZ) return;
    float proc[NEXP];
    float psum = 0.f;
#pragma unroll
    for (int e = 0; e < NEXP; e++) {
        proc[e] = fminf((float)g_count[e], (float)CAPCT);
        psum += proc[e];
    }
    float inv = 1.f / fmaxf(psum, 1.f);
    float lb = 0.f;
#pragma unroll
    for (int e = 0; e < NEXP; e++)
        lb += (g_usage[e] / (float)BTOK) * (proc[e] * inv);
    lb *= (float)NEXP;
    float zl = g_z2 / (float)BTOK;
    out[(size_t)BTOK * DIMSZ] = 0.01f * lb + 0.01f * zl;
}

// ---------------- launch ----------------
extern "C" void kernel_launch(void* const* d_in, const int* in_sizes, int n_in,
                              void* d_out, int out_size) {
    const float* x  = (const float*)d_in[0];
    const float* rw = (const float*)d_in[1];
    const float* w1 = (const float*)d_in[2];
    const float* b1 = (const float*)d_in[3];
    const float* w2 = (const float*)d_in[4];
    const float* b2 = (const float*)d_in[5];
    float* out = (float*)d_out;

    cudaFuncSetAttribute(gemm1_mma, cudaFuncAttributeMaxDynamicSharedMemorySize, SMEM_G);
    cudaFuncSetAttribute(gemm2_mma, cudaFuncAttributeMaxDynamicSharedMemorySize, SMEM_G);

    cudaMemsetAsync(out, 0, (size_t)BTOK * DIMSZ * sizeof(float), 0);
    init_kernel<<<1, 64>>>();
    conv_x_kernel<<<(BTOK * DIMSZ / 4) / 256, 256>>>(x);
    conv_tr_kernel<<<dim3(HID / 32, DIMSZ / 32, NEXP), 256>>>(w1, 0, DIMSZ, HID);
    conv_tr_kernel<<<dim3(DIMSZ / 32, HID / 32, NEXP), 256>>>(w2, 1, HID, DIMSZ);
    router_kernel<<<BTOK / 32, 256>>>(x, rw);
    select_kernel<<<NEXP, 256>>>();
    build_kernel<<<NSLOT / 256, 256>>>();
    gemm1_mma<<<dim3(HID / BN, CAPCT / BM, NEXP), 256, SMEM_G>>>(b1);
    gemm2_mma<<<dim3(DIMSZ / BN, CAPCT / BM, NEXP), 256, SMEM_G>>>(b2, out);
    aux_kernel<<<1, 1>>>(out, out_size);
}

// round 16
// speedup vs baseline: 1.1345x; 1.1345x over previous
#include <cuda_runtime.h>
#include <cuda_fp16.h>
#include <math.h>
#include <stdint.h>

// ---------------- problem constants ----------------
#define BTOK   32768
#define DIMSZ  1024
#define NEXP   8
#define TOPK   2
#define HID    4096
#define CAPCT  10240            // ceil(1.25 * 32768 * 2 / 8)
#define NSLOT  (BTOK * TOPK)    // 65536

// ---------------- GEMM tiling ----------------
#define BM 128
#define BN 128
#define BK 32                   // K elements per chunk (fp16)
#define ROWB 80                 // padded row stride bytes (64 data + 16 pad)
#define RG_A  0
#define RG_B  10240
#define STG_BYTES 20480
#define NSTAGE 3
#define SMEM_G (NSTAGE * STG_BYTES)   // 61440, dynamic (opt-in); 2 CTAs/SM -> 122880

// ---------------- device scratch (static, no allocs) ----------------
__device__ __align__(128) __half g_x16[(size_t)BTOK * DIMSZ];
__device__ __align__(128) __half g_w1t[(size_t)NEXP * HID * DIMSZ]; // [e][n=hid][k=dim]
__device__ __align__(128) __half g_w2t[(size_t)NEXP * DIMSZ * HID]; // [e][n=dim][k=hid]
__device__ __align__(128) __half g_h16[(size_t)NEXP * CAPCT * HID];
__device__ __align__(128) int                g_tok[NEXP * CAPCT];
__device__ __align__(128) float              g_gw[NEXP * CAPCT];
__device__ __align__(128) int                g_topi[NSLOT];
__device__ __align__(128) float              g_topw[NSLOT];
__device__ int                g_count[NEXP];
__device__ int                g_len[NEXP];
__device__ float              g_usage[NEXP];
__device__ float              g_z2;
__device__ unsigned long long g_thr[NEXP];

// ---------------- helpers ----------------
__device__ __forceinline__ uint32_t smem_u32(const void* p) {
    uint32_t a;
    asm("{ .reg .u64 t; cvta.to.shared.u64 t, %1; cvt.u32.u64 %0, t; }" : "=r"(a) : "l"(p));
    return a;
}
__device__ __forceinline__ void cp16(uint32_t d, const void* s) {
    asm volatile("cp.async.cg.shared.global [%0], [%1], 16;" :: "r"(d), "l"(s));
}
__device__ __forceinline__ void cp_commit() { asm volatile("cp.async.commit_group;"); }
__device__ __forceinline__ void cp_wait1()  { asm volatile("cp.async.wait_group 1;"); }

__device__ __forceinline__ void ldsm4(uint32_t* r, uint32_t a) {
    asm volatile("ldmatrix.sync.aligned.m8n8.x4.shared.b16 {%0,%1,%2,%3}, [%4];"
                 : "=r"(r[0]), "=r"(r[1]), "=r"(r[2]), "=r"(r[3]) : "r"(a));
}
__device__ __forceinline__ void mma_f16(float* d, const uint32_t* a, uint32_t b0, uint32_t b1) {
    asm volatile("mma.sync.aligned.m16n8k16.row.col.f32.f16.f16.f32 "
                 "{%0,%1,%2,%3}, {%4,%5,%6,%7}, {%8,%9}, {%0,%1,%2,%3};"
                 : "+f"(d[0]), "+f"(d[1]), "+f"(d[2]), "+f"(d[3])
                 : "r"(a[0]), "r"(a[1]), "r"(a[2]), "r"(a[3]), "r"(b0), "r"(b1));
}

__device__ __forceinline__ unsigned long long make_key(float w, int slot) {
    return ((unsigned long long)__float_as_uint(w) << 32) |
           (unsigned long long)(0xFFFFFFFFu - (unsigned)slot);
}
__device__ __forceinline__ float gelu_exact(float v) {
    return 0.5f * v * (1.0f + erff(v * 0.70710678118654752f));
}

// ---------------- init ----------------
__global__ void init_kernel() {
    int t = threadIdx.x;
    if (t < NEXP) { g_count[t] = 0; g_len[t] = 0; g_usage[t] = 0.f; }
    if (t == 0)   { g_z2 = 0.f; }
}

// ---------------- conversions ----------------
__global__ __launch_bounds__(256) void conv_x_kernel(const float* __restrict__ x) {
    size_t i = (size_t)blockIdx.x * 256 + threadIdx.x;        // float4 index
    float4 v = ((const float4*)x)[i];
    __half2 p0 = __floats2half2_rn(v.x, v.y);
    __half2 p1 = __floats2half2_rn(v.z, v.w);
    ((__half2*)g_x16)[i * 2 + 0] = p0;
    ((__half2*)g_x16)[i * 2 + 1] = p1;
}

// transpose: src [e][K_][N_] fp32 -> dst [e][N_][K_] fp16
// Destination globals bound INSIDE device code (host-passed __device__ symbols
// resolve to the host shadow -> silent ATS writes on GB300; R4/R6 bug).
__global__ __launch_bounds__(256) void conv_tr_kernel(const float* __restrict__ src,
                                                      int which, int K_, int N_) {
    __half* dst = which ? g_w2t : g_w1t;
    __shared__ float t[32][33];
    int e = blockIdx.z;
    src += (size_t)e * K_ * N_;
    dst += (size_t)e * K_ * N_;
    int n0 = blockIdx.x * 32, k0 = blockIdx.y * 32;
    int tx = threadIdx.x & 31, ty = threadIdx.x >> 5;
#pragma unroll
    for (int i = 0; i < 32; i += 8)
        t[ty + i][tx] = src[(size_t)(k0 + ty + i) * N_ + n0 + tx];
    __syncthreads();
#pragma unroll
    for (int i = 0; i < 32; i += 8) {
        float v = t[tx][ty + i];
        dst[(size_t)(n0 + ty + i) * K_ + k0 + tx] = __float2half_rn(v);
    }
}

// ---------------- router ----------------
__global__ __launch_bounds__(256) void router_kernel(const float* __restrict__ x,
                                                     const float* __restrict__ rw) {
    __shared__ float sW[NEXP * DIMSZ];
    __shared__ float s_usage[NEXP];
    __shared__ int   s_count[NEXP];
    __shared__ float s_z2;

    int tid = threadIdx.x;
    for (int i = tid; i < NEXP * DIMSZ; i += 256) sW[i] = rw[i];
    if (tid < NEXP) { s_usage[tid] = 0.f; s_count[tid] = 0; }
    if (tid == 0) s_z2 = 0.f;
    __syncthreads();

    int warp = tid >> 5, lane = tid & 31;
    for (int t = 0; t < 4; t++) {
        int row = blockIdx.x * 32 + warp * 4 + t;
        const float* xr = x + (size_t)row * DIMSZ;
        float acc[NEXP];
#pragma unroll
        for (int e = 0; e < NEXP; e++) acc[e] = 0.f;
        for (int i = lane; i < DIMSZ; i += 32) {
            float xv = xr[i];
#pragma unroll
            for (int e = 0; e < NEXP; e++) acc[e] = fmaf(xv, sW[e * DIMSZ + i], acc[e]);
        }
#pragma unroll
        for (int e = 0; e < NEXP; e++)
#pragma unroll
            for (int off = 16; off; off >>= 1)
                acc[e] += __shfl_xor_sync(0xFFFFFFFFu, acc[e], off);

        if (lane == 0) {
            float m = acc[0];
#pragma unroll
            for (int e = 1; e < NEXP; e++) m = fmaxf(m, acc[e]);
            float p[NEXP]; float se = 0.f;
#pragma unroll
            for (int e = 0; e < NEXP; e++) { p[e] = expf(acc[e] - m); se += p[e]; }
            float inv = 1.f / se;
#pragma unroll
            for (int e = 0; e < NEXP; e++) p[e] *= inv;
            float z = m + logf(se);

            int i0 = 0;
#pragma unroll
            for (int e = 1; e < NEXP; e++) if (acc[e] > acc[i0]) i0 = e;
            int i1 = -1;
#pragma unroll
            for (int e = 0; e < NEXP; e++)
                if (e != i0 && (i1 < 0 || acc[e] > acc[i1])) i1 = e;

            float p0 = p[i0], p1 = p[i1];
            float s = fmaxf(p0 + p1, 1e-9f);
            g_topi[row * 2 + 0] = i0; g_topw[row * 2 + 0] = p0 / s;
            g_topi[row * 2 + 1] = i1; g_topw[row * 2 + 1] = p1 / s;

            atomicAdd(&s_count[i0], 1);
            atomicAdd(&s_count[i1], 1);
#pragma unroll
            for (int e = 0; e < NEXP; e++) atomicAdd(&s_usage[e], p[e]);
            atomicAdd(&s_z2, z * z);
        }
    }
    __syncthreads();
    if (tid < NEXP) {
        atomicAdd(&g_usage[tid], s_usage[tid]);
        atomicAdd(&g_count[tid], s_count[tid]);
    }
    if (tid == 0) atomicAdd(&g_z2, s_z2);
}

// ---------------- exact capacity threshold (radix select, only on overflow) ----------------
__global__ void select_kernel() {
    int e = blockIdx.x;
    if (g_count[e] <= CAPCT) {
        if (threadIdx.x == 0) g_thr[e] = 0ULL;
        return;
    }
    __shared__ unsigned int       hist[256];
    __shared__ unsigned long long s_prefix;
    __shared__ int                s_rem;
    if (threadIdx.x == 0) { s_prefix = 0ULL; s_rem = CAPCT; }

    for (int pass = 7; pass >= 0; pass--) {
        __syncthreads();
        for (int i = threadIdx.x; i < 256; i += blockDim.x) hist[i] = 0u;
        __syncthreads();
        unsigned long long prefix = s_prefix;
        for (int s = threadIdx.x; s < NSLOT; s += blockDim.x) {
            if (g_topi[s] == e) {
                unsigned long long key = make_key(g_topw[s], s);
                bool match = (pass == 7) || ((key >> ((pass + 1) * 8)) == prefix);
                if (match)
                    atomicAdd(&hist[(unsigned)((key >> (pass * 8)) & 255ULL)], 1u);
            }
        }
        __syncthreads();
        if (threadIdx.x == 0) {
            int rem = s_rem;
            int digit = 0;
            for (int b = 255; b >= 0; b--) {
                if ((int)hist[b] >= rem) { digit = b; break; }
                rem -= (int)hist[b];
            }
            s_prefix = (s_prefix << 8) | (unsigned long long)digit;
            s_rem = rem;
        }
    }
    __syncthreads();
    if (threadIdx.x == 0) g_thr[e] = s_prefix;
}

// ---------------- build per-expert token lists ----------------
__global__ void build_kernel() {
    int s = blockIdx.x * blockDim.x + threadIdx.x;
    if (s >= NSLOT) return;
    int e = g_topi[s];
    float w = g_topw[s];
    bool keep = (g_count[e] <= CAPCT) || (make_key(w, s) >= g_thr[e]);
    if (keep) {
        int pos = atomicAdd(&g_len[e], 1);
        g_tok[e * CAPCT + pos] = s >> 1;
        g_gw[e * CAPCT + pos]  = w;
    }
}

// ======================================================================
// Plain fp16 HMMA GEMM core (fp32 accumulate): 32 HMMA/warp/chunk.
// 128x128 CTA tile, K-chunk 32, 3-stage cp.async pipeline.
// 2 CTAs/SM co-residency hides prologue/epilogue/tail bubbles.
// 8 warps: (wm,wn), wm in {0,1} x 64 rows, wn in {0..3} x 32 cols.
// ======================================================================
template <bool IS_G1>
__device__ __forceinline__ void gemm_core(int e, int len, int row0, int col0,
                                          uint32_t sb, float acc[4][4][4]) {
    int tid = threadIdx.x, lane = tid & 31, wid = tid >> 5;
    int wm = wid & 1, wn = wid >> 1;

    // load mapping: row = tid>>1 (0..127), sel = tid&1 (32B half of 64B row)
    int lrow = tid >> 1, lsel = tid & 1;
    const __half *ap, *bp;
    int KTOT;
    if (IS_G1) {
        int gr = row0 + lrow;
        int tok = (gr < len) ? g_tok[e * CAPCT + gr] : 0;
        ap = g_x16 + (size_t)tok * DIMSZ + lsel * 16;
        bp = g_w1t + ((size_t)e * HID + col0 + lrow) * DIMSZ + lsel * 16;
        KTOT = DIMSZ;
    } else {
        ap = g_h16 + ((size_t)e * CAPCT + row0 + lrow) * HID + lsel * 16;
        bp = g_w2t + ((size_t)e * DIMSZ + col0 + lrow) * HID + lsel * 16;
        KTOT = HID;
    }
    const int NK = KTOT / BK;
    uint32_t sdst = sb + lrow * ROWB + lsel * 32;

    auto load_stage = [&](int st, int kc) {
        uint32_t base = sdst + st * STG_BYTES;
        cp16(base + RG_A,      ap + kc);
        cp16(base + RG_A + 16, ap + kc + 8);
        cp16(base + RG_B,      bp + kc);
        cp16(base + RG_B + 16, bp + kc + 8);
    };

    load_stage(0, 0);   cp_commit();
    load_stage(1, BK);  cp_commit();

    // per-lane ldmatrix base offsets (x4: lanes 0-15 rows, lanes 16-31 +16B k-half)
    uint32_t arow = (uint32_t)(wm * 64 + (lane & 15)) * ROWB + ((lane >> 4) * 16);
    uint32_t brow = (uint32_t)(wn * 32 + (lane & 15)) * ROWB + ((lane >> 4) * 16);

    for (int c = 0; c < NK; c++) {
        int st = c % NSTAGE;
        cp_wait1();          // stage c resident (<=1 newer group outstanding)
        __syncthreads();     // also fences stage (c % NSTAGE) reads from last round
        if (c + 2 < NK) load_stage((c + 2) % NSTAGE, (c + 2) * BK);
        cp_commit();

        uint32_t sbase = sb + st * STG_BYTES;
#pragma unroll
        for (int kk = 0; kk < 2; kk++) {
            uint32_t ah[4][4];
#pragma unroll
            for (int mt = 0; mt < 4; mt++)
                ldsm4(ah[mt], sbase + RG_A + arow + mt * (16 * ROWB) + kk * 32);
            uint32_t bh[2][4];
#pragma unroll
            for (int j = 0; j < 2; j++)
                ldsm4(bh[j], sbase + RG_B + brow + j * (16 * ROWB) + kk * 32);
#pragma unroll
            for (int mt = 0; mt < 4; mt++)
#pragma unroll
                for (int j = 0; j < 2; j++)
#pragma unroll
                    for (int s = 0; s < 2; s++)
                        mma_f16(acc[mt][j * 2 + s], ah[mt], bh[j][s], bh[j][s + 2]);
        }
    }
    __syncthreads();
}

// ---------------- GEMM1: h = gelu(gather(x) @ W1 + b1) ----------------
__global__ __launch_bounds__(256, 2) void gemm1_mma(const float* __restrict__ b1) {
    int e = blockIdx.z;
    int len = g_len[e];
    int row0 = blockIdx.y * BM;
    if (row0 >= len) return;
    int col0 = blockIdx.x * BN;

    extern __shared__ __align__(128) char smem_d[];
    uint32_t sb = smem_u32(smem_d);

    float acc[4][4][4];
#pragma unroll
    for (int i = 0; i < 4; i++)
#pragma unroll
        for (int j = 0; j < 4; j++)
#pragma unroll
            for (int k = 0; k < 4; k++) acc[i][j][k] = 0.f;

    gemm_core<true>(e, len, row0, col0, sb, acc);

    int lane = threadIdx.x & 31, wid = threadIdx.x >> 5;
    int wm = wid & 1, wn = wid >> 1;
    const float* bb = b1 + (size_t)e * HID;
#pragma unroll
    for (int mt = 0; mt < 4; mt++) {
        int rA = row0 + wm * 64 + mt * 16 + (lane >> 2);
        int rB = rA + 8;
        bool vA = rA < len, vB = rB < len;
        __half* hA = g_h16 + ((size_t)e * CAPCT + rA) * HID;
        __half* hB = g_h16 + ((size_t)e * CAPCT + rB) * HID;
#pragma unroll
        for (int nt = 0; nt < 4; nt++) {
            int col = col0 + wn * 32 + nt * 8 + (lane & 3) * 2;
            float bv0 = bb[col], bv1 = bb[col + 1];
            if (vA) {
                float x0 = gelu_exact(acc[mt][nt][0] + bv0);
                float x1 = gelu_exact(acc[mt][nt][1] + bv1);
                *(__half2*)(hA + col) = __floats2half2_rn(x0, x1);
            }
            if (vB) {
                float x0 = gelu_exact(acc[mt][nt][2] + bv0);
                float x1 = gelu_exact(acc[mt][nt][3] + bv1);
                *(__half2*)(hB + col) = __floats2half2_rn(x0, x1);
            }
        }
    }
}

// ---------------- GEMM2: out[tok] += gw * (h @ W2 + b2) ----------------
__global__ __launch_bounds__(256, 2) void gemm2_mma(const float* __restrict__ b2,
                                                    float* __restrict__ out) {
    int e = blockIdx.z;
    int len = g_len[e];
    int row0 = blockIdx.y * BM;
    if (row0 >= len) return;
    int col0 = blockIdx.x * BN;

    extern __shared__ __align__(128) char smem_d[];
    uint32_t sb = smem_u32(smem_d);

    float acc[4][4][4];
#pragma unroll
    for (int i = 0; i < 4; i++)
#pragma unroll
        for (int j = 0; j < 4; j++)
#pragma unroll
            for (int k = 0; k < 4; k++) acc[i][j][k] = 0.f;

    gemm_core<false>(e, len, row0, col0, sb, acc);

    int lane = threadIdx.x & 31, wid = threadIdx.x >> 5;
    int wm = wid & 1, wn = wid >> 1;
    const float* bb = b2 + (size_t)e * DIMSZ;
#pragma unroll
    for (int mt = 0; mt < 4; mt++) {
        int rA = row0 + wm * 64 + mt * 16 + (lane >> 2);
        int rB = rA + 8;
        bool vA = rA < len, vB = rB < len;
        int   tokA = vA ? g_tok[e * CAPCT + rA] : 0;
        float gwA  = vA ? g_gw[e * CAPCT + rA]  : 0.f;
        int   tokB = vB ? g_tok[e * CAPCT + rB] : 0;
        float gwB  = vB ? g_gw[e * CAPCT + rB]  : 0.f;
        float* oA = out + (size_t)tokA * DIMSZ;
        float* oB = out + (size_t)tokB * DIMSZ;
#pragma unroll
        for (int nt = 0; nt < 4; nt++) {
            int col = col0 + wn * 32 + nt * 8 + (lane & 3) * 2;
            float bv0 = bb[col], bv1 = bb[col + 1];
            if (vA) {
                atomicAdd(oA + col,     (acc[mt][nt][0] + bv0) * gwA);
                atomicAdd(oA + col + 1, (acc[mt][nt][1] + bv1) * gwA);
            }
            if (vB) {
                atomicAdd(oB + col,     (acc[mt][nt][2] + bv0) * gwB);
                atomicAdd(oB + col + 1, (acc[mt][nt][3] + bv1) * gwB);
            }
        }
    }
}

// ---------------- aux loss ----------------
__global__ void aux_kernel(float* out, int out_size) {
    if ((size_t)out_size <= (size_t)BTOK * DIMSZ) return;
    float proc[NEXP];
    float psum = 0.f;
#pragma unroll
    for (int e = 0; e < NEXP; e++) {
        proc[e] = fminf((float)g_count[e], (float)CAPCT);
        psum += proc[e];
    }
    float inv = 1.f / fmaxf(psum, 1.f);
    float lb = 0.f;
#pragma unroll
    for (int e = 0; e < NEXP; e++)
        lb += (g_usage[e] / (float)BTOK) * (proc[e] * inv);
    lb *= (float)NEXP;
    float zl = g_z2 / (float)BTOK;
    out[(size_t)BTOK * DIMSZ] = 0.01f * lb + 0.01f * zl;
}

// ---------------- launch ----------------
extern "C" void kernel_launch(void* const* d_in, const int* in_sizes, int n_in,
                              void* d_out, int out_size) {
    const float* x  = (const float*)d_in[0];
    const float* rw = (const float*)d_in[1];
    const float* w1 = (const float*)d_in[2];
    const float* b1 = (const float*)d_in[3];
    const float* w2 = (const float*)d_in[4];
    const float* b2 = (const float*)d_in[5];
    float* out = (float*)d_out;

    cudaFuncSetAttribute(gemm1_mma, cudaFuncAttributeMaxDynamicSharedMemorySize, SMEM_G);
    cudaFuncSetAttribute(gemm2_mma, cudaFuncAttributeMaxDynamicSharedMemorySize, SMEM_G);

    cudaMemsetAsync(out, 0, (size_t)BTOK * DIMSZ * sizeof(float), 0);
    init_kernel<<<1, 64>>>();
    conv_x_kernel<<<(BTOK * DIMSZ / 4) / 256, 256>>>(x);
    conv_tr_kernel<<<dim3(HID / 32, DIMSZ / 32, NEXP), 256>>>(w1, 0, DIMSZ, HID);
    conv_tr_kernel<<<dim3(DIMSZ / 32, HID / 32, NEXP), 256>>>(w2, 1, HID, DIMSZ);
    router_kernel<<<BTOK / 32, 256>>>(x, rw);
    select_kernel<<<NEXP, 256>>>();
    build_kernel<<<NSLOT / 256, 256>>>();
    gemm1_mma<<<dim3(HID / BN, CAPCT / BM, NEXP), 256, SMEM_G>>>(b1);
    gemm2_mma<<<dim3(DIMSZ / BN, CAPCT / BM, NEXP), 256, SMEM_G>>>(b2, out);
    aux_kernel<<<1, 1>>>(out, out_size);
}

// round 17
// speedup vs baseline: 1.1750x; 1.0357x over previous
#include <cuda_runtime.h>
#include <cuda_fp16.h>
#include <math.h>
#include <stdint.h>

// ---------------- problem constants ----------------
#define BTOK   32768
#define DIMSZ  1024
#define NEXP   8
#define TOPK   2
#define HID    4096
#define CAPCT  10240            // ceil(1.25 * 32768 * 2 / 8)
#define NSLOT  (BTOK * TOPK)    // 65536

// ---------------- GEMM tiling ----------------
#define BM 128
#define BN 128
#define BK 32                   // K elements per chunk (fp16)
#define ROWB 80                 // padded row stride bytes (64 data + 16 pad)
#define RG_A  0
#define RG_B  10240
#define STG_BYTES 20480
#define NSTAGE 4
#define SMEM_G (NSTAGE * STG_BYTES)   // 81920, dynamic (opt-in)

// ---------------- device scratch (static, no allocs) ----------------
__device__ __align__(128) __half g_x16[(size_t)BTOK * DIMSZ];
__device__ __align__(128) __half g_w1t[(size_t)NEXP * HID * DIMSZ]; // [e][n=hid][k=dim]
__device__ __align__(128) __half g_w2t[(size_t)NEXP * DIMSZ * HID]; // [e][n=dim][k=hid]
__device__ __align__(128) __half g_h16[(size_t)NEXP * CAPCT * HID];
__device__ __align__(128) int                g_tok[NEXP * CAPCT];
__device__ __align__(128) float              g_gw[NEXP * CAPCT];
__device__ __align__(128) int                g_topi[NSLOT];
__device__ __align__(128) float              g_topw[NSLOT];
__device__ int                g_count[NEXP];
__device__ int                g_len[NEXP];
__device__ float              g_usage[NEXP];
__device__ float              g_z2;
__device__ unsigned long long g_thr[NEXP];

// ---------------- helpers ----------------
__device__ __forceinline__ uint32_t smem_u32(const void* p) {
    uint32_t a;
    asm("{ .reg .u64 t; cvta.to.shared.u64 t, %1; cvt.u32.u64 %0, t; }" : "=r"(a) : "l"(p));
    return a;
}
__device__ __forceinline__ void cp16(uint32_t d, const void* s) {
    asm volatile("cp.async.cg.shared.global [%0], [%1], 16;" :: "r"(d), "l"(s));
}
__device__ __forceinline__ void cp_commit() { asm volatile("cp.async.commit_group;"); }
__device__ __forceinline__ void cp_wait2()  { asm volatile("cp.async.wait_group 2;"); }

__device__ __forceinline__ void ldsm4(uint32_t* r, uint32_t a) {
    asm volatile("ldmatrix.sync.aligned.m8n8.x4.shared.b16 {%0,%1,%2,%3}, [%4];"
                 : "=r"(r[0]), "=r"(r[1]), "=r"(r[2]), "=r"(r[3]) : "r"(a));
}
__device__ __forceinline__ void mma_f16(float* d, const uint32_t* a, uint32_t b0, uint32_t b1) {
    asm volatile("mma.sync.aligned.m16n8k16.row.col.f32.f16.f16.f32 "
                 "{%0,%1,%2,%3}, {%4,%5,%6,%7}, {%8,%9}, {%0,%1,%2,%3};"
                 : "+f"(d[0]), "+f"(d[1]), "+f"(d[2]), "+f"(d[3])
                 : "r"(a[0]), "r"(a[1]), "r"(a[2]), "r"(a[3]), "r"(b0), "r"(b1));
}

__device__ __forceinline__ unsigned long long make_key(float w, int slot) {
    return ((unsigned long long)__float_as_uint(w) << 32) |
           (unsigned long long)(0xFFFFFFFFu - (unsigned)slot);
}
__device__ __forceinline__ float gelu_exact(float v) {
    return 0.5f * v * (1.0f + erff(v * 0.70710678118654752f));
}

// ---------------- init ----------------
__global__ void init_kernel() {
    int t = threadIdx.x;
    if (t < NEXP) { g_count[t] = 0; g_len[t] = 0; g_usage[t] = 0.f; }
    if (t == 0)   { g_z2 = 0.f; }
}

// transpose: src [e][K_][N_] fp32 -> dst [e][N_][K_] fp16
// Destination globals bound INSIDE device code (host-passed __device__ symbols
// resolve to the host shadow -> silent ATS writes on GB300; R4/R6 bug).
__global__ __launch_bounds__(256) void conv_tr_kernel(const float* __restrict__ src,
                                                      int which, int K_, int N_) {
    __half* dst = which ? g_w2t : g_w1t;
    __shared__ float t[32][33];
    int e = blockIdx.z;
    src += (size_t)e * K_ * N_;
    dst += (size_t)e * K_ * N_;
    int n0 = blockIdx.x * 32, k0 = blockIdx.y * 32;
    int tx = threadIdx.x & 31, ty = threadIdx.x >> 5;
#pragma unroll
    for (int i = 0; i < 32; i += 8)
        t[ty + i][tx] = src[(size_t)(k0 + ty + i) * N_ + n0 + tx];
    __syncthreads();
#pragma unroll
    for (int i = 0; i < 32; i += 8) {
        float v = t[tx][ty + i];
        dst[(size_t)(n0 + ty + i) * K_ + k0 + tx] = __float2half_rn(v);
    }
}

// ---------------- router (+ fused x -> fp16 conversion) ----------------
__global__ __launch_bounds__(256) void router_kernel(const float* __restrict__ x,
                                                     const float* __restrict__ rw) {
    __shared__ float sW[NEXP * DIMSZ];
    __shared__ float s_usage[NEXP];
    __shared__ int   s_count[NEXP];
    __shared__ float s_z2;

    int tid = threadIdx.x;
    for (int i = tid; i < NEXP * DIMSZ; i += 256) sW[i] = rw[i];
    if (tid < NEXP) { s_usage[tid] = 0.f; s_count[tid] = 0; }
    if (tid == 0) s_z2 = 0.f;
    __syncthreads();

    int warp = tid >> 5, lane = tid & 31;
    for (int t = 0; t < 4; t++) {
        int row = blockIdx.x * 32 + warp * 4 + t;
        const float* xr = x + (size_t)row * DIMSZ;
        __half* xo = g_x16 + (size_t)row * DIMSZ;
        float acc[NEXP];
#pragma unroll
        for (int e = 0; e < NEXP; e++) acc[e] = 0.f;
        for (int i = lane; i < DIMSZ; i += 32) {
            float xv = xr[i];
            xo[i] = __float2half_rn(xv);          // fused conversion
#pragma unroll
            for (int e = 0; e < NEXP; e++) acc[e] = fmaf(xv, sW[e * DIMSZ + i], acc[e]);
        }
#pragma unroll
        for (int e = 0; e < NEXP; e++)
#pragma unroll
            for (int off = 16; off; off >>= 1)
                acc[e] += __shfl_xor_sync(0xFFFFFFFFu, acc[e], off);

        if (lane == 0) {
            float m = acc[0];
#pragma unroll
            for (int e = 1; e < NEXP; e++) m = fmaxf(m, acc[e]);
            float p[NEXP]; float se = 0.f;
#pragma unroll
            for (int e = 0; e < NEXP; e++) { p[e] = expf(acc[e] - m); se += p[e]; }
            float inv = 1.f / se;
#pragma unroll
            for (int e = 0; e < NEXP; e++) p[e] *= inv;
            float z = m + logf(se);

            int i0 = 0;
#pragma unroll
            for (int e = 1; e < NEXP; e++) if (acc[e] > acc[i0]) i0 = e;
            int i1 = -1;
#pragma unroll
            for (int e = 0; e < NEXP; e++)
                if (e != i0 && (i1 < 0 || acc[e] > acc[i1])) i1 = e;

            float p0 = p[i0], p1 = p[i1];
            float s = fmaxf(p0 + p1, 1e-9f);
            g_topi[row * 2 + 0] = i0; g_topw[row * 2 + 0] = p0 / s;
            g_topi[row * 2 + 1] = i1; g_topw[row * 2 + 1] = p1 / s;

            atomicAdd(&s_count[i0], 1);
            atomicAdd(&s_count[i1], 1);
#pragma unroll
            for (int e = 0; e < NEXP; e++) atomicAdd(&s_usage[e], p[e]);
            atomicAdd(&s_z2, z * z);
        }
    }
    __syncthreads();
    if (tid < NEXP) {
        atomicAdd(&g_usage[tid], s_usage[tid]);
        atomicAdd(&g_count[tid], s_count[tid]);
    }
    if (tid == 0) atomicAdd(&g_z2, s_z2);
}

// ---------------- exact capacity threshold (radix select, only on overflow) ----------------
__global__ void select_kernel() {
    int e = blockIdx.x;
    if (g_count[e] <= CAPCT) {
        if (threadIdx.x == 0) g_thr[e] = 0ULL;
        return;
    }
    __shared__ unsigned int       hist[256];
    __shared__ unsigned long long s_prefix;
    __shared__ int                s_rem;
    if (threadIdx.x == 0) { s_prefix = 0ULL; s_rem = CAPCT; }

    for (int pass = 7; pass >= 0; pass--) {
        __syncthreads();
        for (int i = threadIdx.x; i < 256; i += blockDim.x) hist[i] = 0u;
        __syncthreads();
        unsigned long long prefix = s_prefix;
        for (int s = threadIdx.x; s < NSLOT; s += blockDim.x) {
            if (g_topi[s] == e) {
                unsigned long long key = make_key(g_topw[s], s);
                bool match = (pass == 7) || ((key >> ((pass + 1) * 8)) == prefix);
                if (match)
                    atomicAdd(&hist[(unsigned)((key >> (pass * 8)) & 255ULL)], 1u);
            }
        }
        __syncthreads();
        if (threadIdx.x == 0) {
            int rem = s_rem;
            int digit = 0;
            for (int b = 255; b >= 0; b--) {
                if ((int)hist[b] >= rem) { digit = b; break; }
                rem -= (int)hist[b];
            }
            s_prefix = (s_prefix << 8) | (unsigned long long)digit;
            s_rem = rem;
        }
    }
    __syncthreads();
    if (threadIdx.x == 0) g_thr[e] = s_prefix;
}

// ---------------- build per-expert token lists ----------------
__global__ void build_kernel() {
    int s = blockIdx.x * blockDim.x + threadIdx.x;
    if (s >= NSLOT) return;
    int e = g_topi[s];
    float w = g_topw[s];
    bool keep = (g_count[e] <= CAPCT) || (make_key(w, s) >= g_thr[e]);
    if (keep) {
        int pos = atomicAdd(&g_len[e], 1);
        g_tok[e * CAPCT + pos] = s >> 1;
        g_gw[e * CAPCT + pos]  = w;
    }
}

// ======================================================================
// Plain fp16 HMMA GEMM core (fp32 accumulate): 32 HMMA/warp/chunk.
// 128x128 CTA tile, K-chunk 32, 4-stage cp.async pipeline with prefetch
// distance 3 (wait_group 2) -- deeper latency hiding, identical load
// geometry to the proven BK=32/ROWB=80 configuration.
// 8 warps: (wm,wn), wm in {0,1} x 64 rows, wn in {0..3} x 32 cols.
// ======================================================================
template <bool IS_G1>
__device__ __forceinline__ void gemm_core(int e, int len, int row0, int col0,
                                          uint32_t sb, float acc[4][4][4]) {
    int tid = threadIdx.x, lane = tid & 31, wid = tid >> 5;
    int wm = wid & 1, wn = wid >> 1;

    // load mapping: row = tid>>1 (0..127), sel = tid&1 (32B half of 64B row)
    int lrow = tid >> 1, lsel = tid & 1;
    const __half *ap, *bp;
    int KTOT;
    if (IS_G1) {
        int gr = row0 + lrow;
        int tok = (gr < len) ? g_tok[e * CAPCT + gr] : 0;
        ap = g_x16 + (size_t)tok * DIMSZ + lsel * 16;
        bp = g_w1t + ((size_t)e * HID + col0 + lrow) * DIMSZ + lsel * 16;
        KTOT = DIMSZ;
    } else {
        ap = g_h16 + ((size_t)e * CAPCT + row0 + lrow) * HID + lsel * 16;
        bp = g_w2t + ((size_t)e * DIMSZ + col0 + lrow) * HID + lsel * 16;
        KTOT = HID;
    }
    const int NK = KTOT / BK;
    uint32_t sdst = sb + lrow * ROWB + lsel * 32;

    auto load_stage = [&](int st, int kc) {
        uint32_t base = sdst + st * STG_BYTES;
        cp16(base + RG_A,      ap + kc);
        cp16(base + RG_A + 16, ap + kc + 8);
        cp16(base + RG_B,      bp + kc);
        cp16(base + RG_B + 16, bp + kc + 8);
    };

    load_stage(0, 0);        cp_commit();
    load_stage(1, BK);       cp_commit();
    load_stage(2, 2 * BK);   cp_commit();

    // per-lane ldmatrix base offsets (x4: lanes 0-15 rows, lanes 16-31 +16B k-half)
    uint32_t arow = (uint32_t)(wm * 64 + (lane & 15)) * ROWB + ((lane >> 4) * 16);
    uint32_t brow = (uint32_t)(wn * 32 + (lane & 15)) * ROWB + ((lane >> 4) * 16);

    for (int c = 0; c < NK; c++) {
        int st = c % NSTAGE;
        cp_wait2();          // stage c resident (<=2 newer groups outstanding)
        __syncthreads();     // also fences stage (c % NSTAGE) reads from last round
        if (c + 3 < NK) load_stage((c + 3) % NSTAGE, (c + 3) * BK);
        cp_commit();

        uint32_t sbase = sb + st * STG_BYTES;
#pragma unroll
        for (int kk = 0; kk < 2; kk++) {
            uint32_t ah[4][4];
#pragma unroll
            for (int mt = 0; mt < 4; mt++)
                ldsm4(ah[mt], sbase + RG_A + arow + mt * (16 * ROWB) + kk * 32);
            uint32_t bh[2][4];
#pragma unroll
            for (int j = 0; j < 2; j++)
                ldsm4(bh[j], sbase + RG_B + brow + j * (16 * ROWB) + kk * 32);
#pragma unroll
            for (int mt = 0; mt < 4; mt++)
#pragma unroll
                for (int j = 0; j < 2; j++)
#pragma unroll
                    for (int s = 0; s < 2; s++)
                        mma_f16(acc[mt][j * 2 + s], ah[mt], bh[j][s], bh[j][s + 2]);
        }
    }
    __syncthreads();
}

// ---------------- GEMM1: h = gelu(gather(x) @ W1 + b1) ----------------
__global__ __launch_bounds__(256, 1) void gemm1_mma(const float* __restrict__ b1) {
    int e = blockIdx.z;
    int len = g_len[e];
    int row0 = blockIdx.y * BM;
    if (row0 >= len) return;
    int col0 = blockIdx.x * BN;

    extern __shared__ __align__(128) char smem_d[];
    uint32_t sb = smem_u32(smem_d);

    float acc[4][4][4];
#pragma unroll
    for (int i = 0; i < 4; i++)
#pragma unroll
        for (int j = 0; j < 4; j++)
#pragma unroll
            for (int k = 0; k < 4; k++) acc[i][j][k] = 0.f;

    gemm_core<true>(e, len, row0, col0, sb, acc);

    int lane = threadIdx.x & 31, wid = threadIdx.x >> 5;
    int wm = wid & 1, wn = wid >> 1;
    const float* bb = b1 + (size_t)e * HID;
#pragma unroll
    for (int mt = 0; mt < 4; mt++) {
        int rA = row0 + wm * 64 + mt * 16 + (lane >> 2);
        int rB = rA + 8;
        bool vA = rA < len, vB = rB < len;
        __half* hA = g_h16 + ((size_t)e * CAPCT + rA) * HID;
        __half* hB = g_h16 + ((size_t)e * CAPCT + rB) * HID;
#pragma unroll
        for (int nt = 0; nt < 4; nt++) {
            int col = col0 + wn * 32 + nt * 8 + (lane & 3) * 2;
            float bv0 = bb[col], bv1 = bb[col + 1];
            if (vA) {
                float x0 = gelu_exact(acc[mt][nt][0] + bv0);
                float x1 = gelu_exact(acc[mt][nt][1] + bv1);
                *(__half2*)(hA + col) = __floats2half2_rn(x0, x1);
            }
            if (vB) {
                float x0 = gelu_exact(acc[mt][nt][2] + bv0);
                float x1 = gelu_exact(acc[mt][nt][3] + bv1);
                *(__half2*)(hB + col) = __floats2half2_rn(x0, x1);
            }
        }
    }
}

// ---------------- GEMM2: out[tok] += gw * (h @ W2 + b2) ----------------
__global__ __launch_bounds__(256, 1) void gemm2_mma(const float* __restrict__ b2,
                                                    float* __restrict__ out) {
    int e = blockIdx.z;
    int len = g_len[e];
    int row0 = blockIdx.y * BM;
    if (row0 >= len) return;
    int col0 = blockIdx.x * BN;

    extern __shared__ __align__(128) char smem_d[];
    uint32_t sb = smem_u32(smem_d);

    float acc[4][4][4];
#pragma unroll
    for (int i = 0; i < 4; i++)
#pragma unroll
        for (int j = 0; j < 4; j++)
#pragma unroll
            for (int k = 0; k < 4; k++) acc[i][j][k] = 0.f;

    gemm_core<false>(e, len, row0, col0, sb, acc);

    int lane = threadIdx.x & 31, wid = threadIdx.x >> 5;
    int wm = wid & 1, wn = wid >> 1;
    const float* bb = b2 + (size_t)e * DIMSZ;
#pragma unroll
    for (int mt = 0; mt < 4; mt++) {
        int rA = row0 + wm * 64 + mt * 16 + (lane >> 2);
        int rB = rA + 8;
        bool vA = rA < len, vB = rB < len;
        int   tokA = vA ? g_tok[e * CAPCT + rA] : 0;
        float gwA  = vA ? g_gw[e * CAPCT + rA]  : 0.f;
        int   tokB = vB ? g_tok[e * CAPCT + rB] : 0;
        float gwB  = vB ? g_gw[e * CAPCT + rB]  : 0.f;
        float* oA = out + (size_t)tokA * DIMSZ;
        float* oB = out + (size_t)tokB * DIMSZ;
#pragma unroll
        for (int nt = 0; nt < 4; nt++) {
            int col = col0 + wn * 32 + nt * 8 + (lane & 3) * 2;
            float bv0 = bb[col], bv1 = bb[col + 1];
            if (vA) {
                atomicAdd(oA + col,     (acc[mt][nt][0] + bv0) * gwA);
                atomicAdd(oA + col + 1, (acc[mt][nt][1] + bv1) * gwA);
            }
            if (vB) {
                atomicAdd(oB + col,     (acc[mt][nt][2] + bv0) * gwB);
                atomicAdd(oB + col + 1, (acc[mt][nt][3] + bv1) * gwB);
            }
        }
    }
}

// ---------------- aux loss ----------------
__global__ void aux_kernel(float* out, int out_size) {
    if ((size_t)out_size <= (size_t)BTOK * DIMSZ) return;
    float proc[NEXP];
    float psum = 0.f;
#pragma unroll
    for (int e = 0; e < NEXP; e++) {
        proc[e] = fminf((float)g_count[e], (float)CAPCT);
        psum += proc[e];
    }
    float inv = 1.f / fmaxf(psum, 1.f);
    float lb = 0.f;
#pragma unroll
    for (int e = 0; e < NEXP; e++)
        lb += (g_usage[e] / (float)BTOK) * (proc[e] * inv);
    lb *= (float)NEXP;
    float zl = g_z2 / (float)BTOK;
    out[(size_t)BTOK * DIMSZ] = 0.01f * lb + 0.01f * zl;
}

// ---------------- launch ----------------
extern "C" void kernel_launch(void* const* d_in, const int* in_sizes, int n_in,
                              void* d_out, int out_size) {
    const float* x  = (const float*)d_in[0];
    const float* rw = (const float*)d_in[1];
    const float* w1 = (const float*)d_in[2];
    const float* b1 = (const float*)d_in[3];
    const float* w2 = (const float*)d_in[4];
    const float* b2 = (const float*)d_in[5];
    float* out = (float*)d_out;

    cudaFuncSetAttribute(gemm1_mma, cudaFuncAttributeMaxDynamicSharedMemorySize, SMEM_G);
    cudaFuncSetAttribute(gemm2_mma, cudaFuncAttributeMaxDynamicSharedMemorySize, SMEM_G);

    cudaMemsetAsync(out, 0, (size_t)BTOK * DIMSZ * sizeof(float), 0);
    init_kernel<<<1, 64>>>();
    conv_tr_kernel<<<dim3(HID / 32, DIMSZ / 32, NEXP), 256>>>(w1, 0, DIMSZ, HID);
    conv_tr_kernel<<<dim3(DIMSZ / 32, HID / 32, NEXP), 256>>>(w2, 1, HID, DIMSZ);
    router_kernel<<<BTOK / 32, 256>>>(x, rw);
    select_kernel<<<NEXP, 256>>>();
    build_kernel<<<NSLOT / 256, 256>>>();
    gemm1_mma<<<dim3(HID / BN, CAPCT / BM, NEXP), 256, SMEM_G>>>(b1);
    gemm2_mma<<<dim3(DIMSZ / BN, CAPCT / BM, NEXP), 256, SMEM_G>>>(b2, out);
    aux_kernel<<<1, 1>>>(out, out_size);
}